// round 4
// baseline (speedup 1.0000x reference)
#include <cuda_runtime.h>
#include <math.h>

#define BNUM 32
#define CLIPD 1024
#define OCN 512
#define KTOP 30
#define NROI (BNUM*KTOP)     // 960
#define NANCH 2304           // 16*16*9

// ---------------- scratch (static device globals; no runtime alloc) -------------
__device__ float g_x[BNUM*256*OCN];          // conv output, layout [b*256+pos][oc]
__device__ float g_scores[BNUM*NANCH];
__device__ float g_boxes[BNUM*NANCH*4];
__device__ float g_rois[NROI*4];
__device__ int   g_valid[NROI];
__device__ float g_integral[BNUM*257*257];
__device__ int   g_labels[NROI];
__device__ float g_pooled[NROI*CLIPD];
__device__ float g_proj[NROI*256];
__device__ float g_li[NROI];
__device__ int   g_active[NROI];

// anchor w/h for a = si*3+ri, scales {8,16,32}, ratios {0.5,1,2}, w=s*sqrt(r), h=s/sqrt(r)
__constant__ float c_AW[9] = {5.656854249492381f, 8.f, 11.313708498984761f,
                              11.313708498984761f, 16.f, 22.627416997969522f,
                              22.627416997969522f, 32.f, 45.254833995939045f};
__constant__ float c_AH[9] = {11.313708498984761f, 8.f, 5.656854249492381f,
                              22.627416997969522f, 16.f, 11.313708498984761f,
                              45.254833995939045f, 32.f, 22.627416997969522f};

// ---------------- 1. conv 3x3 SAME, 1024->512, + bias + relu --------------------
// grid (16 oc-blocks of 32, 32 batches), 128 threads.
// thread: 4 spatial positions (row segment) x 16 oc accumulators.
__global__ __launch_bounds__(128) void conv_kernel(const float* __restrict__ clip,
                                                   const float* __restrict__ W,
                                                   const float* __restrict__ bias) {
    __shared__ __align__(16) float in_s[8][18][20];   // zero-padded halo
    __shared__ __align__(16) float w_s[8][9][32];     // [c][tap][oc32]
    const int t = threadIdx.x;
    const int ocb = blockIdx.x, b = blockIdx.y;

    // zero entire input tile once (borders persist as zero-padding)
    float* ip = &in_s[0][0][0];
    for (int k = t; k < 8*18*20; k += 128) ip[k] = 0.f;

    const int g = t & 63, h = t >> 6;
    const int i = g >> 2, j0 = (g & 3) << 2;

    float acc[4][16];
    #pragma unroll
    for (int p = 0; p < 4; p++)
        #pragma unroll
        for (int k = 0; k < 16; k++) acc[p][k] = 0.f;

    for (int chunk = 0; chunk < 128; chunk++) {
        const int c0 = chunk * 8;
        __syncthreads();
        // load 8 channels x 16x16 positions; clip layout: [(1+pos)*32768 + b*1024 + c]
        for (int idx = t; idx < 512; idx += 128) {
            const int pos = idx >> 1, half = idx & 1;
            const float4 v = *(const float4*)(clip + (size_t)(1 + pos)*32768 + b*1024 + c0 + half*4);
            const int ii = (pos >> 4) + 1, jj = (pos & 15) + 1;
            in_s[half*4+0][ii][jj] = v.x;
            in_s[half*4+1][ii][jj] = v.y;
            in_s[half*4+2][ii][jj] = v.z;
            in_s[half*4+3][ii][jj] = v.w;
        }
        // load 32 oc x 8 c x 9 taps of weights
        for (int idx = t; idx < 2304; idx += 128) {
            const int oo = idx / 72, rem = idx % 72;
            const int c = rem / 9, tap = rem % 9;
            w_s[c][tap][oo] = W[(size_t)(ocb*32 + oo)*9216 + (size_t)(c0 + c)*9 + tap];
        }
        __syncthreads();

        #pragma unroll 1
        for (int c = 0; c < 8; c++) {
            float r[3][6];
            #pragma unroll
            for (int di = 0; di < 3; di++)
                #pragma unroll
                for (int dj = 0; dj < 6; dj++)
                    r[di][dj] = in_s[c][i + di][j0 + dj];
            #pragma unroll
            for (int ki = 0; ki < 3; ki++)
                #pragma unroll
                for (int kj = 0; kj < 3; kj++) {
                    const int tap = ki*3 + kj;
                    const float4* wp = (const float4*)&w_s[c][tap][h*16];
                    const float4 wA = wp[0], wB = wp[1], wC = wp[2], wD = wp[3];
                    const float wv[16] = {wA.x, wA.y, wA.z, wA.w, wB.x, wB.y, wB.z, wB.w,
                                          wC.x, wC.y, wC.z, wC.w, wD.x, wD.y, wD.z, wD.w};
                    #pragma unroll
                    for (int p = 0; p < 4; p++) {
                        const float v = r[ki][p + kj];
                        #pragma unroll
                        for (int k = 0; k < 16; k++)
                            acc[p][k] = fmaf(v, wv[k], acc[p][k]);
                    }
                }
        }
    }

    #pragma unroll
    for (int p = 0; p < 4; p++) {
        const int pos = i*16 + j0 + p;
        #pragma unroll
        for (int k = 0; k < 16; k++) {
            const int oc = ocb*32 + h*16 + k;
            const float val = acc[p][k] + bias[oc];
            g_x[((size_t)(b*256 + pos))*512 + oc] = fmaxf(val, 0.f);
        }
    }
}

// ---------------- 2. cls/reg heads + decode + sigmoid ---------------------------
// grid (256 positions, 32 batches), 64 threads
__global__ __launch_bounds__(64) void head_kernel(const float* __restrict__ cls_w,
                                                  const float* __restrict__ cls_b,
                                                  const float* __restrict__ reg_w,
                                                  const float* __restrict__ reg_b) {
    const int b = blockIdx.y, pos = blockIdx.x, t = threadIdx.x;
    __shared__ float xs[512];
    __shared__ float ov[45];
    for (int k = t; k < 512; k += 64) xs[k] = g_x[((size_t)(b*256 + pos))*512 + k];
    __syncthreads();
    if (t < 45) {
        const float* wr = (t < 9) ? (cls_w + t*512) : (reg_w + (t - 9)*512);
        float s = (t < 9) ? cls_b[t] : reg_b[t - 9];
        for (int k = 0; k < 512; k++) s = fmaf(xs[k], wr[k], s);
        ov[t] = s;
    }
    __syncthreads();
    if (t < 9) {
        const int a = t;
        const int i = pos >> 4, j = pos & 15;
        const float xc = (j + 0.5f) * 16.f, yc = (i + 0.5f) * 16.f;
        const float aw = c_AW[a], ah = c_AH[a];
        const float r0 = ov[9 + a*4 + 0], r1 = ov[9 + a*4 + 1];
        const float r2 = ov[9 + a*4 + 2], r3 = ov[9 + a*4 + 3];
        const float cx = r0*aw + xc, cy = r1*ah + yc;
        const float pw = expf(r2)*aw, ph = expf(r3)*ah;
        float x1 = fminf(fmaxf(cx - 0.5f*pw, 0.f), 256.f);
        float y1 = fminf(fmaxf(cy - 0.5f*ph, 0.f), 256.f);
        float x2 = fminf(fmaxf(cx + 0.5f*pw, 0.f), 256.f);
        float y2 = fminf(fmaxf(cy + 0.5f*ph, 0.f), 256.f);
        if (x2 - x1 < 1.f) x2 = x1 + 1.f;
        if (y2 - y1 < 1.f) y2 = y1 + 1.f;
        const int ai = pos*9 + a;
        g_scores[b*NANCH + ai] = 1.f / (1.f + expf(-ov[a]));
        float* bp = &g_boxes[((size_t)b*NANCH + ai)*4];
        bp[0] = x1; bp[1] = y1; bp[2] = x2; bp[3] = y2;
    }
}

// ---------------- 3. per-batch top-30 (stable) + sequential NMS -----------------
__global__ __launch_bounds__(256) void topk_nms_kernel() {
    const int b = blockIdx.x, t = threadIdx.x;
    __shared__ float sc[NANCH];
    __shared__ float rv[256];
    __shared__ int   ri[256];
    __shared__ int   sel[KTOP];
    __shared__ float bx[KTOP][4];
    __shared__ int   keep[KTOP];
    for (int k = t; k < NANCH; k += 256) sc[k] = g_scores[b*NANCH + k];
    __syncthreads();
    for (int it = 0; it < KTOP; it++) {
        float bv = -3.f; int bi = NANCH;
        for (int k = t; k < NANCH; k += 256) {
            const float v = sc[k];
            if (v > bv || (v == bv && k < bi)) { bv = v; bi = k; }
        }
        rv[t] = bv; ri[t] = bi;
        __syncthreads();
        for (int s = 128; s > 0; s >>= 1) {
            if (t < s) {
                const float v2 = rv[t + s]; const int i2 = ri[t + s];
                if (v2 > rv[t] || (v2 == rv[t] && i2 < ri[t])) { rv[t] = v2; ri[t] = i2; }
            }
            __syncthreads();
        }
        if (t == 0) { sel[it] = ri[0]; sc[ri[0]] = -2.f; }
        __syncthreads();
    }
    if (t < KTOP) {
        const float* bp = &g_boxes[((size_t)b*NANCH + sel[t])*4];
        bx[t][0] = bp[0]; bx[t][1] = bp[1]; bx[t][2] = bp[2]; bx[t][3] = bp[3];
        keep[t] = 1;
    }
    __syncthreads();
    for (int ii = 0; ii < KTOP; ii++) {
        if (t < KTOP && t > ii && keep[ii]) {
            const float ax1 = bx[ii][0], ay1 = bx[ii][1], ax2 = bx[ii][2], ay2 = bx[ii][3];
            const float bx1 = bx[t][0], by1 = bx[t][1], bx2 = bx[t][2], by2 = bx[t][3];
            const float areaA = (ax2 - ax1) * (ay2 - ay1);
            const float areaB = (bx2 - bx1) * (by2 - by1);
            const float iw = fmaxf(fminf(ax2, bx2) - fmaxf(ax1, bx1), 0.f);
            const float ih = fmaxf(fminf(ay2, by2) - fmaxf(ay1, by1), 0.f);
            const float inter = iw * ih;
            const float iou = inter / (areaA + areaB - inter);
            if (iou > 0.85f) keep[t] = 0;
        }
        __syncthreads();
    }
    if (t < KTOP) {
        const int r = b*KTOP + t;
        g_rois[r*4 + 0] = bx[t][0];
        g_rois[r*4 + 1] = bx[t][1];
        g_rois[r*4 + 2] = bx[t][2];
        g_rois[r*4 + 3] = bx[t][3];
        g_valid[r] = keep[t];
    }
}

// ---------------- 4. integral image of gt_masks ---------------------------------
__global__ __launch_bounds__(256) void integral_rows(const float* __restrict__ gt) {
    const int b = blockIdx.x, t = threadIdx.x;
    g_integral[((size_t)b*257 + 0)*257 + t] = 0.f;
    if (t == 0) g_integral[((size_t)b*257)*257 + 256] = 0.f;
    g_integral[((size_t)b*257 + t + 1)*257 + 0] = 0.f;
    const float* gr = gt + (size_t)b*65536 + (size_t)t*256;
    float s = 0.f;
    float* Ir = &g_integral[((size_t)b*257 + t + 1)*257 + 1];
    for (int j = 0; j < 256; j++) { s += gr[j]; Ir[j] = s; }
}

__global__ __launch_bounds__(288) void integral_cols() {
    const int b = blockIdx.x, t = threadIdx.x;
    if (t >= 257) return;
    float* base = &g_integral[(size_t)b*257*257];
    float s = 0.f;
    for (int i = 1; i <= 256; i++) {
        s += base[i*257 + t];
        base[i*257 + t] = s;
    }
}

// ---------------- 5. ROI-align mean (1024 ch) + label ---------------------------
__global__ __launch_bounds__(256) void roialign_kernel(const float* __restrict__ clip) {
    const int r = blockIdx.x, t = threadIdx.x;
    const int b = r / KTOP;
    __shared__ int   o00[49], o01[49], o10[49], o11[49];
    __shared__ float w00[49], w01[49], w10[49], w11[49];
    __shared__ float roi[4];
    if (t < 4) roi[t] = g_rois[r*4 + t];
    __syncthreads();
    if (t < 49) {
        const int py = t / 7, px = t % 7;
        const float sc = 1.f / 16.f;
        const float x1f = roi[0]*sc, y1f = roi[1]*sc;
        const float rw = fmaxf(roi[2]*sc - x1f, 1.f);
        const float rh = fmaxf(roi[3]*sc - y1f, 1.f);
        const float X = x1f + (px + 0.5f) * (rw / 7.f);
        const float Y = y1f + (py + 0.5f) * (rh / 7.f);
        const bool ok = (Y > -1.f) && (Y < 16.f) && (X > -1.f) && (X < 16.f);
        const float Xc = fminf(fmaxf(X, 0.f), 15.f);
        const float Yc = fminf(fmaxf(Y, 0.f), 15.f);
        const int x0 = (int)floorf(Xc), y0 = (int)floorf(Yc);
        const int x1i = min(x0 + 1, 15), y1i = min(y0 + 1, 15);
        const float lx = Xc - (float)x0, ly = Yc - (float)y0;
        const float hx = 1.f - lx, hy = 1.f - ly;
        const float okf = ok ? 1.f : 0.f;
        o00[t] = (1 + y0*16  + x0 )*32768 + b*1024;
        o01[t] = (1 + y0*16  + x1i)*32768 + b*1024;
        o10[t] = (1 + y1i*16 + x0 )*32768 + b*1024;
        o11[t] = (1 + y1i*16 + x1i)*32768 + b*1024;
        w00[t] = hy*hx*okf; w01[t] = hy*lx*okf; w10[t] = ly*hx*okf; w11[t] = ly*lx*okf;
    }
    __syncthreads();
    for (int c = t; c < 1024; c += 256) {
        float s = 0.f;
        for (int p = 0; p < 49; p++) {
            s += w00[p]*clip[o00[p] + c] + w01[p]*clip[o01[p] + c]
               + w10[p]*clip[o10[p] + c] + w11[p]*clip[o11[p] + c];
        }
        g_pooled[(size_t)r*1024 + c] = s / 49.f;
    }
    if (t == 0) {
        const int x1 = min(max((int)roi[0], 0), 256);
        const int y1 = min(max((int)roi[1], 0), 256);
        const int x2 = min(max((int)roi[2], 0), 256);
        const int y2 = min(max((int)roi[3], 0), 256);
        const float* I = &g_integral[(size_t)b*257*257];
        const float s = I[y2*257 + x2] - I[y1*257 + x2] - I[y2*257 + x1] + I[y1*257 + x1];
        const int cnt = (y2 - y1) * (x2 - x1);
        g_labels[r] = (cnt > 0) && (s / (float)max(cnt, 1) > 0.5f) ? 1 : 0;
    }
}

// ---------------- 6. 2-layer projection MLP + row normalize ---------------------
__global__ __launch_bounds__(256) void mlp_kernel(const float* __restrict__ w1,
                                                  const float* __restrict__ b1,
                                                  const float* __restrict__ w2,
                                                  const float* __restrict__ b2) {
    const int r = blockIdx.x, t = threadIdx.x;
    __shared__ float pr[1024];
    __shared__ float hs[256];
    __shared__ float ps[256];
    __shared__ float red[256];
    for (int k = t; k < 1024; k += 256) pr[k] = g_pooled[(size_t)r*1024 + k];
    __syncthreads();
    {
        float s = b1[t];
        const float* wr = w1 + (size_t)t*1024;
        for (int k = 0; k < 1024; k++) s = fmaf(pr[k], wr[k], s);
        hs[t] = fmaxf(s, 0.f);
    }
    __syncthreads();
    {
        float s = b2[t];
        const float* wr = w2 + (size_t)t*256;
        for (int k = 0; k < 256; k++) s = fmaf(hs[k], wr[k], s);
        ps[t] = s;
        red[t] = s * s;
    }
    __syncthreads();
    for (int st = 128; st > 0; st >>= 1) { if (t < st) red[t] += red[t + st]; __syncthreads(); }
    const float dn = fmaxf(sqrtf(red[0]), 1e-12f);
    g_proj[(size_t)r*256 + t] = ps[t] / dn;
}

// ---------------- 7. SupCon per-row loss ----------------------------------------
__global__ __launch_bounds__(256) void supcon_kernel() {
    const int i = blockIdx.x, t = threadIdx.x;
    __shared__ float nfi[256];
    __shared__ float rp[256], rd[256];
    __shared__ int   rc[256];
    nfi[t] = g_proj[(size_t)i*256 + t];
    __syncthreads();
    const int vi = g_valid[i], li = g_labels[i];
    float psum = 0.f, dsum = 0.f; int pcnt = 0;
    if (vi) {
        for (int j = t; j < NROI; j += 256) {
            if (j == i || !g_valid[j]) continue;
            const float* pj = &g_proj[(size_t)j*256];
            float d = 0.f;
            for (int k = 0; k < 256; k++) d = fmaf(nfi[k], pj[k], d);
            const float es = expf(d / 0.07f);
            dsum += es;
            if (g_labels[j] == li) { psum += es; pcnt++; }
        }
    }
    rp[t] = psum; rd[t] = dsum; rc[t] = pcnt;
    __syncthreads();
    for (int st = 128; st > 0; st >>= 1) {
        if (t < st) { rp[t] += rp[t + st]; rd[t] += rd[t + st]; rc[t] += rc[t + st]; }
        __syncthreads();
    }
    if (t == 0) {
        const float ratio = rp[0] / (rd[0] + 1e-12f);
        const float l = -logf(ratio + 1e-12f);
        const int act = vi && (rc[0] > 0);
        g_li[i] = act ? l : 0.f;
        g_active[i] = act;
    }
}

// ---------------- 8. final reduction --------------------------------------------
__global__ __launch_bounds__(256) void final_kernel(float* __restrict__ out) {
    const int t = threadIdx.x;
    __shared__ float rs[256];
    __shared__ int   rc[256];
    float s = 0.f; int c = 0;
    for (int k = t; k < NROI; k += 256) { s += g_li[k]; c += g_active[k]; }
    rs[t] = s; rc[t] = c;
    __syncthreads();
    for (int st = 128; st > 0; st >>= 1) {
        if (t < st) { rs[t] += rs[t + st]; rc[t] += rc[t + st]; }
        __syncthreads();
    }
    if (t == 0) out[0] = (rc[0] > 0) ? rs[0] / (float)max(rc[0], 1) : 0.f;
}

// ---------------- launch --------------------------------------------------------
extern "C" void kernel_launch(void* const* d_in, const int* in_sizes, int n_in,
                              void* d_out, int out_size) {
    const float* clip   = (const float*)d_in[0];
    const float* gt     = (const float*)d_in[1];
    const float* conv_w = (const float*)d_in[2];
    const float* conv_b = (const float*)d_in[3];
    const float* cls_w  = (const float*)d_in[4];
    const float* cls_b  = (const float*)d_in[5];
    const float* reg_w  = (const float*)d_in[6];
    const float* reg_b  = (const float*)d_in[7];
    const float* w1     = (const float*)d_in[8];
    const float* b1     = (const float*)d_in[9];
    const float* w2     = (const float*)d_in[10];
    const float* b2     = (const float*)d_in[11];
    float* out = (float*)d_out;

    conv_kernel<<<dim3(16, 32), 128>>>(clip, conv_w, conv_b);
    head_kernel<<<dim3(256, 32), 64>>>(cls_w, cls_b, reg_w, reg_b);
    topk_nms_kernel<<<32, 256>>>();
    integral_rows<<<32, 256>>>(gt);
    integral_cols<<<32, 288>>>();
    roialign_kernel<<<NROI, 256>>>(clip);
    mlp_kernel<<<NROI, 256>>>(w1, b1, w2, b2);
    supcon_kernel<<<NROI, 256>>>();
    final_kernel<<<1, 256>>>(out);
}

// round 5
// speedup vs baseline: 1.9451x; 1.9451x over previous
#include <cuda_runtime.h>
#include <math.h>

#define BNUM 32
#define CLIPD 1024
#define OCN 512
#define KTOP 30
#define NROI (BNUM*KTOP)     // 960
#define NANCH 2304           // 16*16*9
#define FULLM 0xFFFFFFFFu

// ---------------- scratch (static device globals; no runtime alloc) -------------
__device__ float g_x[BNUM*256*OCN];          // conv output, layout [b*256+pos][oc]
__device__ float g_scores[BNUM*NANCH];
__device__ float g_boxes[BNUM*NANCH*4];
__device__ float g_rois[NROI*4];
__device__ int   g_valid[NROI];
__device__ float g_integral[BNUM*257*257];
__device__ int   g_labels[NROI];
__device__ float g_pooled[NROI*CLIPD];
__device__ float g_proj[NROI*256];
__device__ float g_li[NROI];
__device__ int   g_active[NROI];

// anchor w/h for a = si*3+ri, scales {8,16,32}, ratios {0.5,1,2}, w=s*sqrt(r), h=s/sqrt(r)
__constant__ float c_AW[9] = {5.656854249492381f, 8.f, 11.313708498984761f,
                              11.313708498984761f, 16.f, 22.627416997969522f,
                              22.627416997969522f, 32.f, 45.254833995939045f};
__constant__ float c_AH[9] = {11.313708498984761f, 8.f, 5.656854249492381f,
                              22.627416997969522f, 16.f, 11.313708498984761f,
                              45.254833995939045f, 32.f, 22.627416997969522f};

// ---------------- 1. conv 3x3 SAME, 1024->512, + bias + relu --------------------
// (unchanged: FFMA-issue-bound at the fp32 roofline)
__global__ __launch_bounds__(128) void conv_kernel(const float* __restrict__ clip,
                                                   const float* __restrict__ W,
                                                   const float* __restrict__ bias) {
    __shared__ __align__(16) float in_s[8][18][20];
    __shared__ __align__(16) float w_s[8][9][32];
    const int t = threadIdx.x;
    const int ocb = blockIdx.x, b = blockIdx.y;

    float* ip = &in_s[0][0][0];
    for (int k = t; k < 8*18*20; k += 128) ip[k] = 0.f;

    const int g = t & 63, h = t >> 6;
    const int i = g >> 2, j0 = (g & 3) << 2;

    float acc[4][16];
    #pragma unroll
    for (int p = 0; p < 4; p++)
        #pragma unroll
        for (int k = 0; k < 16; k++) acc[p][k] = 0.f;

    for (int chunk = 0; chunk < 128; chunk++) {
        const int c0 = chunk * 8;
        __syncthreads();
        for (int idx = t; idx < 512; idx += 128) {
            const int pos = idx >> 1, half = idx & 1;
            const float4 v = *(const float4*)(clip + (size_t)(1 + pos)*32768 + b*1024 + c0 + half*4);
            const int ii = (pos >> 4) + 1, jj = (pos & 15) + 1;
            in_s[half*4+0][ii][jj] = v.x;
            in_s[half*4+1][ii][jj] = v.y;
            in_s[half*4+2][ii][jj] = v.z;
            in_s[half*4+3][ii][jj] = v.w;
        }
        for (int idx = t; idx < 2304; idx += 128) {
            const int oo = idx / 72, rem = idx % 72;
            const int c = rem / 9, tap = rem % 9;
            w_s[c][tap][oo] = W[(size_t)(ocb*32 + oo)*9216 + (size_t)(c0 + c)*9 + tap];
        }
        __syncthreads();

        #pragma unroll 1
        for (int c = 0; c < 8; c++) {
            float r[3][6];
            #pragma unroll
            for (int di = 0; di < 3; di++)
                #pragma unroll
                for (int dj = 0; dj < 6; dj++)
                    r[di][dj] = in_s[c][i + di][j0 + dj];
            #pragma unroll
            for (int ki = 0; ki < 3; ki++)
                #pragma unroll
                for (int kj = 0; kj < 3; kj++) {
                    const int tap = ki*3 + kj;
                    const float4* wp = (const float4*)&w_s[c][tap][h*16];
                    const float4 wA = wp[0], wB = wp[1], wC = wp[2], wD = wp[3];
                    const float wv[16] = {wA.x, wA.y, wA.z, wA.w, wB.x, wB.y, wB.z, wB.w,
                                          wC.x, wC.y, wC.z, wC.w, wD.x, wD.y, wD.z, wD.w};
                    #pragma unroll
                    for (int p = 0; p < 4; p++) {
                        const float v = r[ki][p + kj];
                        #pragma unroll
                        for (int k = 0; k < 16; k++)
                            acc[p][k] = fmaf(v, wv[k], acc[p][k]);
                    }
                }
        }
    }

    #pragma unroll
    for (int p = 0; p < 4; p++) {
        const int pos = i*16 + j0 + p;
        #pragma unroll
        for (int k = 0; k < 16; k++) {
            const int oc = ocb*32 + h*16 + k;
            const float val = acc[p][k] + bias[oc];
            g_x[((size_t)(b*256 + pos))*512 + oc] = fmaxf(val, 0.f);
        }
    }
}

// ---------------- 2. cls/reg heads + decode + sigmoid ---------------------------
// grid (8 pos-groups, 32 batches), 256 threads. Warp computes 4 positions with
// lane-strided (coalesced) k + shuffle reduction.
__global__ __launch_bounds__(256) void head_kernel(const float* __restrict__ cls_w,
                                                   const float* __restrict__ cls_b,
                                                   const float* __restrict__ reg_w,
                                                   const float* __restrict__ reg_b) {
    const int b = blockIdx.y, grp = blockIdx.x;
    const int t = threadIdx.x, w = t >> 5, lane = t & 31;
    __shared__ float ovs[32][48];

    // preload 4 x-rows per warp, lane-strided over k (coalesced 128B)
    float xr[4][16];
    #pragma unroll
    for (int pp = 0; pp < 4; pp++) {
        const size_t row = (size_t)(b*256 + grp*32 + w*4 + pp);
        #pragma unroll
        for (int q = 0; q < 16; q++)
            xr[pp][q] = g_x[row*512 + q*32 + lane];
    }

    for (int o = 0; o < 45; o++) {
        const float* wr = (o < 9) ? (cls_w + o*512) : (reg_w + (o - 9)*512);
        float wv[16];
        #pragma unroll
        for (int q = 0; q < 16; q++) wv[q] = wr[q*32 + lane];
        #pragma unroll
        for (int pp = 0; pp < 4; pp++) {
            float s = 0.f;
            #pragma unroll
            for (int q = 0; q < 16; q++) s = fmaf(xr[pp][q], wv[q], s);
            #pragma unroll
            for (int off = 16; off > 0; off >>= 1) s += __shfl_xor_sync(FULLM, s, off);
            if (lane == 0) ovs[w*4 + pp][o] = s;
        }
    }
    __syncthreads();

    // decode: 32 positions x 9 anchors = 288 items
    for (int idx = t; idx < 288; idx += 256) {
        const int pl = idx / 9, a = idx % 9;
        const int pos = grp*32 + pl;
        const int i = pos >> 4, j = pos & 15;
        const float xc = (j + 0.5f) * 16.f, yc = (i + 0.5f) * 16.f;
        const float aw = c_AW[a], ah = c_AH[a];
        const float logit = ovs[pl][a] + cls_b[a];
        const float r0 = ovs[pl][9 + a*4 + 0] + reg_b[a*4 + 0];
        const float r1 = ovs[pl][9 + a*4 + 1] + reg_b[a*4 + 1];
        const float r2 = ovs[pl][9 + a*4 + 2] + reg_b[a*4 + 2];
        const float r3 = ovs[pl][9 + a*4 + 3] + reg_b[a*4 + 3];
        const float cx = r0*aw + xc, cy = r1*ah + yc;
        const float pw = expf(r2)*aw, ph = expf(r3)*ah;
        float x1 = fminf(fmaxf(cx - 0.5f*pw, 0.f), 256.f);
        float y1 = fminf(fmaxf(cy - 0.5f*ph, 0.f), 256.f);
        float x2 = fminf(fmaxf(cx + 0.5f*pw, 0.f), 256.f);
        float y2 = fminf(fmaxf(cy + 0.5f*ph, 0.f), 256.f);
        if (x2 - x1 < 1.f) x2 = x1 + 1.f;
        if (y2 - y1 < 1.f) y2 = y1 + 1.f;
        const int ai = pos*9 + a;
        g_scores[b*NANCH + ai] = 1.f / (1.f + expf(-logit));
        float* bp = &g_boxes[((size_t)b*NANCH + ai)*4];
        bp[0] = x1; bp[1] = y1; bp[2] = x2; bp[3] = y2;
    }
}

// ---------------- 3. per-batch top-30 (stable) + sequential NMS -----------------
__global__ __launch_bounds__(256) void topk_nms_kernel() {
    const int b = blockIdx.x, t = threadIdx.x;
    __shared__ float sc[NANCH];
    __shared__ float rv[256];
    __shared__ int   ri[256];
    __shared__ int   sel[KTOP];
    __shared__ float bx[KTOP][4];
    __shared__ int   keep[KTOP];
    for (int k = t; k < NANCH; k += 256) sc[k] = g_scores[b*NANCH + k];
    __syncthreads();
    for (int it = 0; it < KTOP; it++) {
        float bv = -3.f; int bi = NANCH;
        for (int k = t; k < NANCH; k += 256) {
            const float v = sc[k];
            if (v > bv || (v == bv && k < bi)) { bv = v; bi = k; }
        }
        rv[t] = bv; ri[t] = bi;
        __syncthreads();
        for (int s = 128; s > 0; s >>= 1) {
            if (t < s) {
                const float v2 = rv[t + s]; const int i2 = ri[t + s];
                if (v2 > rv[t] || (v2 == rv[t] && i2 < ri[t])) { rv[t] = v2; ri[t] = i2; }
            }
            __syncthreads();
        }
        if (t == 0) { sel[it] = ri[0]; sc[ri[0]] = -2.f; }
        __syncthreads();
    }
    if (t < KTOP) {
        const float* bp = &g_boxes[((size_t)b*NANCH + sel[t])*4];
        bx[t][0] = bp[0]; bx[t][1] = bp[1]; bx[t][2] = bp[2]; bx[t][3] = bp[3];
        keep[t] = 1;
    }
    __syncthreads();
    for (int ii = 0; ii < KTOP; ii++) {
        if (t < KTOP && t > ii && keep[ii]) {
            const float ax1 = bx[ii][0], ay1 = bx[ii][1], ax2 = bx[ii][2], ay2 = bx[ii][3];
            const float bx1 = bx[t][0], by1 = bx[t][1], bx2 = bx[t][2], by2 = bx[t][3];
            const float areaA = (ax2 - ax1) * (ay2 - ay1);
            const float areaB = (bx2 - bx1) * (by2 - by1);
            const float iw = fmaxf(fminf(ax2, bx2) - fmaxf(ax1, bx1), 0.f);
            const float ih = fmaxf(fminf(ay2, by2) - fmaxf(ay1, by1), 0.f);
            const float inter = iw * ih;
            const float iou = inter / (areaA + areaB - inter);
            if (iou > 0.85f) keep[t] = 0;
        }
        __syncthreads();
    }
    if (t < KTOP) {
        const int r = b*KTOP + t;
        g_rois[r*4 + 0] = bx[t][0];
        g_rois[r*4 + 1] = bx[t][1];
        g_rois[r*4 + 2] = bx[t][2];
        g_rois[r*4 + 3] = bx[t][3];
        g_valid[r] = keep[t];
    }
}

// ---------------- 4. integral image: warp-scan rows, tiled column scan ----------
// grid (32 rowgroups, 32 batches), 256 threads: warp per row, shuffle scan.
__global__ __launch_bounds__(256) void integral_rows(const float* __restrict__ gt) {
    const int b = blockIdx.y, t = threadIdx.x;
    const int w = t >> 5, lane = t & 31;
    const int row = blockIdx.x * 8 + w;
    if (blockIdx.x == 0) {
        for (int idx = t; idx < 257; idx += 256)
            g_integral[((size_t)b*257)*257 + idx] = 0.f;   // top zero row
    }
    const float* gr = gt + (size_t)b*65536 + (size_t)row*256;
    float* Ir = g_integral + ((size_t)b*257 + row + 1)*257;
    if (lane == 0) Ir[0] = 0.f;                             // left zero col
    float carry = 0.f;
    #pragma unroll
    for (int chunk = 0; chunk < 8; chunk++) {
        float v = gr[chunk*32 + lane];
        #pragma unroll
        for (int off = 1; off < 32; off <<= 1) {
            const float n = __shfl_up_sync(FULLM, v, off);
            if (lane >= off) v += n;
        }
        Ir[1 + chunk*32 + lane] = carry + v;
        carry += __shfl_sync(FULLM, v, 31);
    }
}

// grid 32 (b), 256 threads: 32-row tiles staged through shared for coalescing.
__global__ __launch_bounds__(256) void integral_cols() {
    __shared__ float tile[32][264];
    const int b = blockIdx.x, t = threadIdx.x;
    float* base = &g_integral[(size_t)b*257*257];
    float s0 = 0.f, s1 = 0.f;  // thread t owns col t; thread 0 also col 256
    for (int ti = 0; ti < 8; ti++) {
        const int r0 = ti*32 + 1;
        #pragma unroll 4
        for (int rr = 0; rr < 32; rr++) {
            tile[rr][t] = base[(size_t)(r0 + rr)*257 + t];
            if (t == 0) tile[rr][256] = base[(size_t)(r0 + rr)*257 + 256];
        }
        __syncthreads();
        #pragma unroll 4
        for (int rr = 0; rr < 32; rr++) {
            s0 += tile[rr][t];  tile[rr][t] = s0;
            if (t == 0) { s1 += tile[rr][256]; tile[rr][256] = s1; }
        }
        __syncthreads();
        #pragma unroll 4
        for (int rr = 0; rr < 32; rr++) {
            base[(size_t)(r0 + rr)*257 + t] = tile[rr][t];
            if (t == 0) base[(size_t)(r0 + rr)*257 + 256] = tile[rr][256];
        }
        __syncthreads();
    }
}

// ---------------- 5. ROI-align mean (1024 ch, float4) + label -------------------
__global__ __launch_bounds__(256) void roialign_kernel(const float* __restrict__ clip) {
    const int r = blockIdx.x, t = threadIdx.x;
    const int b = r / KTOP;
    __shared__ int   o00[49], o01[49], o10[49], o11[49];   // float4 indices
    __shared__ float w00[49], w01[49], w10[49], w11[49];
    __shared__ float roi[4];
    if (t < 4) roi[t] = g_rois[r*4 + t];
    __syncthreads();
    if (t < 49) {
        const int py = t / 7, px = t % 7;
        const float sc = 1.f / 16.f;
        const float x1f = roi[0]*sc, y1f = roi[1]*sc;
        const float rw = fmaxf(roi[2]*sc - x1f, 1.f);
        const float rh = fmaxf(roi[3]*sc - y1f, 1.f);
        const float X = x1f + (px + 0.5f) * (rw / 7.f);
        const float Y = y1f + (py + 0.5f) * (rh / 7.f);
        const bool ok = (Y > -1.f) && (Y < 16.f) && (X > -1.f) && (X < 16.f);
        const float Xc = fminf(fmaxf(X, 0.f), 15.f);
        const float Yc = fminf(fmaxf(Y, 0.f), 15.f);
        const int x0 = (int)floorf(Xc), y0 = (int)floorf(Yc);
        const int x1i = min(x0 + 1, 15), y1i = min(y0 + 1, 15);
        const float lx = Xc - (float)x0, ly = Yc - (float)y0;
        const float hx = 1.f - lx, hy = 1.f - ly;
        const float okf = ok ? 1.f : 0.f;
        o00[t] = (1 + y0*16  + x0 )*8192 + b*256;
        o01[t] = (1 + y0*16  + x1i)*8192 + b*256;
        o10[t] = (1 + y1i*16 + x0 )*8192 + b*256;
        o11[t] = (1 + y1i*16 + x1i)*8192 + b*256;
        w00[t] = hy*hx*okf; w01[t] = hy*lx*okf; w10[t] = ly*hx*okf; w11[t] = ly*lx*okf;
    }
    __syncthreads();
    const float4* clip4 = (const float4*)clip;
    float4 s = make_float4(0.f, 0.f, 0.f, 0.f);
    for (int p = 0; p < 49; p++) {
        const float4 a = clip4[o00[p] + t];
        const float4 bb = clip4[o01[p] + t];
        const float4 c = clip4[o10[p] + t];
        const float4 d = clip4[o11[p] + t];
        const float wa = w00[p], wb = w01[p], wc = w10[p], wd = w11[p];
        s.x += wa*a.x + wb*bb.x + wc*c.x + wd*d.x;
        s.y += wa*a.y + wb*bb.y + wc*c.y + wd*d.y;
        s.z += wa*a.z + wb*bb.z + wc*c.z + wd*d.z;
        s.w += wa*a.w + wb*bb.w + wc*c.w + wd*d.w;
    }
    const float inv = 1.f/49.f;
    float4* po = (float4*)&g_pooled[(size_t)r*1024];
    po[t] = make_float4(s.x*inv, s.y*inv, s.z*inv, s.w*inv);
    if (t == 0) {
        const int x1 = min(max((int)roi[0], 0), 256);
        const int y1 = min(max((int)roi[1], 0), 256);
        const int x2 = min(max((int)roi[2], 0), 256);
        const int y2 = min(max((int)roi[3], 0), 256);
        const float* I = &g_integral[(size_t)b*257*257];
        const float sI = I[y2*257 + x2] - I[y1*257 + x2] - I[y2*257 + x1] + I[y1*257 + x1];
        const int cnt = (y2 - y1) * (x2 - x1);
        g_labels[r] = (cnt > 0) && (sI / (float)max(cnt, 1) > 0.5f) ? 1 : 0;
    }
}

// ---------------- 6. projection MLP, 4 ROIs per block, warp-per-output ----------
#define RPB 4
__global__ __launch_bounds__(256) void mlp_kernel(const float* __restrict__ w1,
                                                  const float* __restrict__ b1,
                                                  const float* __restrict__ w2,
                                                  const float* __restrict__ b2) {
    const int r0 = blockIdx.x * RPB, t = threadIdx.x;
    const int w = t >> 5, lane = t & 31;
    __shared__ float pr[RPB][1024];
    __shared__ float hs[RPB][256];
    __shared__ float ps[RPB][256];
    __shared__ float dn[RPB];
    for (int idx = t; idx < RPB*1024; idx += 256)
        pr[idx >> 10][idx & 1023] = g_pooled[(size_t)r0*1024 + idx];
    __syncthreads();
    // layer 1: 256 outputs, warp-per-output, lane-strided k (coalesced)
    for (int m = 0; m < 32; m++) {
        const int o = m*8 + w;
        float a0 = 0.f, a1 = 0.f, a2 = 0.f, a3 = 0.f;
        const float* wr = w1 + (size_t)o*1024;
        #pragma unroll 8
        for (int q = 0; q < 32; q++) {
            const float wv = wr[q*32 + lane];
            a0 = fmaf(wv, pr[0][q*32 + lane], a0);
            a1 = fmaf(wv, pr[1][q*32 + lane], a1);
            a2 = fmaf(wv, pr[2][q*32 + lane], a2);
            a3 = fmaf(wv, pr[3][q*32 + lane], a3);
        }
        #pragma unroll
        for (int off = 16; off > 0; off >>= 1) {
            a0 += __shfl_xor_sync(FULLM, a0, off);
            a1 += __shfl_xor_sync(FULLM, a1, off);
            a2 += __shfl_xor_sync(FULLM, a2, off);
            a3 += __shfl_xor_sync(FULLM, a3, off);
        }
        if (lane == 0) {
            const float bb = b1[o];
            hs[0][o] = fmaxf(a0 + bb, 0.f);
            hs[1][o] = fmaxf(a1 + bb, 0.f);
            hs[2][o] = fmaxf(a2 + bb, 0.f);
            hs[3][o] = fmaxf(a3 + bb, 0.f);
        }
    }
    __syncthreads();
    // layer 2
    for (int m = 0; m < 32; m++) {
        const int o = m*8 + w;
        float a0 = 0.f, a1 = 0.f, a2 = 0.f, a3 = 0.f;
        const float* wr = w2 + (size_t)o*256;
        #pragma unroll
        for (int q = 0; q < 8; q++) {
            const float wv = wr[q*32 + lane];
            a0 = fmaf(wv, hs[0][q*32 + lane], a0);
            a1 = fmaf(wv, hs[1][q*32 + lane], a1);
            a2 = fmaf(wv, hs[2][q*32 + lane], a2);
            a3 = fmaf(wv, hs[3][q*32 + lane], a3);
        }
        #pragma unroll
        for (int off = 16; off > 0; off >>= 1) {
            a0 += __shfl_xor_sync(FULLM, a0, off);
            a1 += __shfl_xor_sync(FULLM, a1, off);
            a2 += __shfl_xor_sync(FULLM, a2, off);
            a3 += __shfl_xor_sync(FULLM, a3, off);
        }
        if (lane == 0) {
            const float bb = b2[o];
            ps[0][o] = a0 + bb; ps[1][o] = a1 + bb;
            ps[2][o] = a2 + bb; ps[3][o] = a3 + bb;
        }
    }
    __syncthreads();
    // row norms: warp r handles row r
    if (w < RPB) {
        float ss = 0.f;
        #pragma unroll
        for (int q = 0; q < 8; q++) {
            const float v = ps[w][q*32 + lane];
            ss = fmaf(v, v, ss);
        }
        #pragma unroll
        for (int off = 16; off > 0; off >>= 1) ss += __shfl_xor_sync(FULLM, ss, off);
        if (lane == 0) dn[w] = fmaxf(sqrtf(ss), 1e-12f);
    }
    __syncthreads();
    for (int idx = t; idx < RPB*256; idx += 256) {
        const int r = idx >> 8, o = idx & 255;
        g_proj[(size_t)(r0 + r)*256 + o] = ps[r][o] / dn[r];
    }
}

// ---------------- 7. SupCon loss, 4 anchors per block, warp-per-j ---------------
#define IPB 4
__global__ __launch_bounds__(256) void supcon_kernel() {
    const int i0 = blockIdx.x * IPB, t = threadIdx.x;
    const int w = t >> 5, lane = t & 31;
    __shared__ float nfi[IPB][256];
    __shared__ int   jv[NROI];
    __shared__ int   jl[NROI];
    __shared__ float w_ps[8][IPB], w_ds[8][IPB];
    __shared__ int   w_pc[8][IPB];
    for (int idx = t; idx < IPB*256; idx += 256)
        nfi[idx >> 8][idx & 255] = g_proj[(size_t)i0*256 + idx];
    for (int idx = t; idx < NROI; idx += 256) { jv[idx] = g_valid[idx]; jl[idx] = g_labels[idx]; }
    __syncthreads();

    int li[IPB];
    #pragma unroll
    for (int i = 0; i < IPB; i++) li[i] = jl[i0 + i];

    float ps[IPB] = {0.f, 0.f, 0.f, 0.f};
    float ds[IPB] = {0.f, 0.f, 0.f, 0.f};
    int   pc[IPB] = {0, 0, 0, 0};

    for (int j = w; j < NROI; j += 8) {
        if (!jv[j]) continue;
        const float* pj = &g_proj[(size_t)j*256];
        float d0 = 0.f, d1 = 0.f, d2 = 0.f, d3 = 0.f;
        #pragma unroll
        for (int q = 0; q < 8; q++) {
            const float v = pj[q*32 + lane];
            d0 = fmaf(v, nfi[0][q*32 + lane], d0);
            d1 = fmaf(v, nfi[1][q*32 + lane], d1);
            d2 = fmaf(v, nfi[2][q*32 + lane], d2);
            d3 = fmaf(v, nfi[3][q*32 + lane], d3);
        }
        #pragma unroll
        for (int off = 16; off > 0; off >>= 1) {
            d0 += __shfl_xor_sync(FULLM, d0, off);
            d1 += __shfl_xor_sync(FULLM, d1, off);
            d2 += __shfl_xor_sync(FULLM, d2, off);
            d3 += __shfl_xor_sync(FULLM, d3, off);
        }
        const int lj = jl[j];
        float dd[IPB] = {d0, d1, d2, d3};
        #pragma unroll
        for (int i = 0; i < IPB; i++) {
            if (j == i0 + i) continue;
            const float es = expf(dd[i] / 0.07f);
            ds[i] += es;
            if (lj == li[i]) { ps[i] += es; pc[i]++; }
        }
    }
    if (lane == 0) {
        #pragma unroll
        for (int i = 0; i < IPB; i++) { w_ps[w][i] = ps[i]; w_ds[w][i] = ds[i]; w_pc[w][i] = pc[i]; }
    }
    __syncthreads();
    if (t < IPB) {
        float P = 0.f, D = 0.f; int C = 0;
        #pragma unroll
        for (int ww = 0; ww < 8; ww++) { P += w_ps[ww][t]; D += w_ds[ww][t]; C += w_pc[ww][t]; }
        const float ratio = P / (D + 1e-12f);
        const float l = -logf(ratio + 1e-12f);
        const int act = jv[i0 + t] && (C > 0);
        g_li[i0 + t] = act ? l : 0.f;
        g_active[i0 + t] = act;
    }
}

// ---------------- 8. final reduction --------------------------------------------
__global__ __launch_bounds__(256) void final_kernel(float* __restrict__ out) {
    const int t = threadIdx.x;
    __shared__ float rs[256];
    __shared__ int   rc[256];
    float s = 0.f; int c = 0;
    for (int k = t; k < NROI; k += 256) { s += g_li[k]; c += g_active[k]; }
    rs[t] = s; rc[t] = c;
    __syncthreads();
    for (int st = 128; st > 0; st >>= 1) {
        if (t < st) { rs[t] += rs[t + st]; rc[t] += rc[t + st]; }
        __syncthreads();
    }
    if (t == 0) out[0] = (rc[0] > 0) ? rs[0] / (float)max(rc[0], 1) : 0.f;
}

// ---------------- launch --------------------------------------------------------
extern "C" void kernel_launch(void* const* d_in, const int* in_sizes, int n_in,
                              void* d_out, int out_size) {
    const float* clip   = (const float*)d_in[0];
    const float* gt     = (const float*)d_in[1];
    const float* conv_w = (const float*)d_in[2];
    const float* conv_b = (const float*)d_in[3];
    const float* cls_w  = (const float*)d_in[4];
    const float* cls_b  = (const float*)d_in[5];
    const float* reg_w  = (const float*)d_in[6];
    const float* reg_b  = (const float*)d_in[7];
    const float* w1     = (const float*)d_in[8];
    const float* b1     = (const float*)d_in[9];
    const float* w2     = (const float*)d_in[10];
    const float* b2     = (const float*)d_in[11];
    float* out = (float*)d_out;

    conv_kernel<<<dim3(16, 32), 128>>>(clip, conv_w, conv_b);
    integral_rows<<<dim3(32, 32), 256>>>(gt);   // independent of conv; overlaps
    integral_cols<<<32, 256>>>();
    head_kernel<<<dim3(8, 32), 256>>>(cls_w, cls_b, reg_w, reg_b);
    topk_nms_kernel<<<32, 256>>>();
    roialign_kernel<<<NROI, 256>>>(clip);
    mlp_kernel<<<NROI/RPB, 256>>>(w1, b1, w2, b2);
    supcon_kernel<<<NROI/IPB, 256>>>();
    final_kernel<<<1, 256>>>(out);
}

// round 6
// speedup vs baseline: 2.1459x; 1.1033x over previous
#include <cuda_runtime.h>
#include <math.h>

#define BNUM 32
#define CLIPD 1024
#define OCN 512
#define KTOP 30
#define NROI (BNUM*KTOP)     // 960
#define NANCH 2304           // 16*16*9
#define FULLM 0xFFFFFFFFu

typedef unsigned long long u64t;

// packed f32x2 helpers (Blackwell-only; ptxas never emits FFMA2 from C++)
__device__ __forceinline__ u64t fma2(u64t a, u64t b, u64t c) {
    u64t d;
    asm("fma.rn.f32x2 %0, %1, %2, %3;" : "=l"(d) : "l"(a), "l"(b), "l"(c));
    return d;
}
__device__ __forceinline__ u64t pack2(float v) {
    u64t d; unsigned r = __float_as_uint(v);
    asm("mov.b64 %0, {%1, %1};" : "=l"(d) : "r"(r));
    return d;
}
__device__ __forceinline__ void unpack2(u64t v, float& lo, float& hi) {
    unsigned a, b;
    asm("mov.b64 {%0, %1}, %2;" : "=r"(a), "=r"(b) : "l"(v));
    lo = __uint_as_float(a); hi = __uint_as_float(b);
}

// ---------------- scratch (static device globals; no runtime alloc) -------------
__device__ float g_x[BNUM*256*OCN];          // conv output, layout [b*256+pos][oc]
__device__ float g_scores[BNUM*NANCH];
__device__ float g_boxes[BNUM*NANCH*4];
__device__ float g_rois[NROI*4];
__device__ int   g_valid[NROI];
__device__ float g_integral[BNUM*257*257];
__device__ int   g_labels[NROI];
__device__ float g_pooled[NROI*CLIPD];
__device__ float g_proj[NROI*256];
__device__ float g_li[NROI];
__device__ int   g_active[NROI];

// anchor w/h for a = si*3+ri, scales {8,16,32}, ratios {0.5,1,2}
__constant__ float c_AW[9] = {5.656854249492381f, 8.f, 11.313708498984761f,
                              11.313708498984761f, 16.f, 22.627416997969522f,
                              22.627416997969522f, 32.f, 45.254833995939045f};
__constant__ float c_AH[9] = {11.313708498984761f, 8.f, 5.656854249492381f,
                              22.627416997969522f, 16.f, 11.313708498984761f,
                              45.254833995939045f, 32.f, 22.627416997969522f};

// ---------------- 1. conv 3x3 SAME, 1024->512, + bias + relu (f32x2) ------------
// grid (16 oc-blocks of 32, 32 batches), 128 threads.
// thread: 4 spatial positions x 16 oc, accumulated as 8 packed f32x2 pairs.
__global__ __launch_bounds__(128) void conv_kernel(const float* __restrict__ clip,
                                                   const float* __restrict__ W,
                                                   const float* __restrict__ bias) {
    __shared__ __align__(16) float in_s[8][18][20];
    __shared__ __align__(16) float w_s[8][9][32];
    const int t = threadIdx.x;
    const int ocb = blockIdx.x, b = blockIdx.y;

    float* ip = &in_s[0][0][0];
    for (int k = t; k < 8*18*20; k += 128) ip[k] = 0.f;

    const int g = t & 63, h = t >> 6;
    const int i = g >> 2, j0 = (g & 3) << 2;

    u64t acc[4][8];
    #pragma unroll
    for (int p = 0; p < 4; p++)
        #pragma unroll
        for (int k = 0; k < 8; k++) acc[p][k] = 0ull;

    for (int chunk = 0; chunk < 128; chunk++) {
        const int c0 = chunk * 8;
        __syncthreads();
        for (int idx = t; idx < 512; idx += 128) {
            const int pos = idx >> 1, half = idx & 1;
            const float4 v = *(const float4*)(clip + (size_t)(1 + pos)*32768 + b*1024 + c0 + half*4);
            const int ii = (pos >> 4) + 1, jj = (pos & 15) + 1;
            in_s[half*4+0][ii][jj] = v.x;
            in_s[half*4+1][ii][jj] = v.y;
            in_s[half*4+2][ii][jj] = v.z;
            in_s[half*4+3][ii][jj] = v.w;
        }
        for (int idx = t; idx < 2304; idx += 128) {
            const int oo = idx / 72, rem = idx % 72;
            const int c = rem / 9, tap = rem % 9;
            w_s[c][tap][oo] = W[(size_t)(ocb*32 + oo)*9216 + (size_t)(c0 + c)*9 + tap];
        }
        __syncthreads();

        #pragma unroll 1
        for (int c = 0; c < 8; c++) {
            #pragma unroll
            for (int ki = 0; ki < 3; ki++) {
                // 6-wide row window, packed (v,v)
                u64t rv[6];
                #pragma unroll
                for (int dj = 0; dj < 6; dj++)
                    rv[dj] = pack2(in_s[c][i + ki][j0 + dj]);
                #pragma unroll
                for (int kj = 0; kj < 3; kj++) {
                    const int tap = ki*3 + kj;
                    const ulonglong2* wp = (const ulonglong2*)&w_s[c][tap][h*16];
                    const ulonglong2 wA = wp[0], wB = wp[1], wC = wp[2], wD = wp[3];
                    const u64t wv[8] = {wA.x, wA.y, wB.x, wB.y, wC.x, wC.y, wD.x, wD.y};
                    #pragma unroll
                    for (int p = 0; p < 4; p++) {
                        const u64t v = rv[p + kj];
                        #pragma unroll
                        for (int k = 0; k < 8; k++)
                            acc[p][k] = fma2(v, wv[k], acc[p][k]);
                    }
                }
            }
        }
    }

    #pragma unroll
    for (int p = 0; p < 4; p++) {
        const int pos = i*16 + j0 + p;
        float* orow = &g_x[((size_t)(b*256 + pos))*512 + ocb*32 + h*16];
        #pragma unroll
        for (int k = 0; k < 8; k++) {
            float lo, hi;
            unpack2(acc[p][k], lo, hi);
            const float2 bb = *(const float2*)&bias[ocb*32 + h*16 + 2*k];
            float2 o;
            o.x = fmaxf(lo + bb.x, 0.f);
            o.y = fmaxf(hi + bb.y, 0.f);
            *(float2*)&orow[2*k] = o;
        }
    }
}

// ---------------- 2. cls/reg heads + decode + sigmoid ---------------------------
// grid (8 pos-groups, 32 batches), 256 threads. Weights staged once in dynamic
// shared (90KB) — removes repeated L2-latency loads.
extern __shared__ float s_hw[];   // [45][512]
__global__ __launch_bounds__(256) void head_kernel(const float* __restrict__ cls_w,
                                                   const float* __restrict__ cls_b,
                                                   const float* __restrict__ reg_w,
                                                   const float* __restrict__ reg_b) {
    const int b = blockIdx.y, grp = blockIdx.x;
    const int t = threadIdx.x, w = t >> 5, lane = t & 31;
    __shared__ float ovs[32][48];

    for (int idx = t; idx < 45*512; idx += 256) {
        const int o = idx >> 9, k = idx & 511;
        s_hw[idx] = (o < 9) ? cls_w[o*512 + k] : reg_w[(o - 9)*512 + k];
    }

    // preload 4 x-rows per warp, lane-strided over k (coalesced 128B)
    float xr[4][16];
    #pragma unroll
    for (int pp = 0; pp < 4; pp++) {
        const size_t row = (size_t)(b*256 + grp*32 + w*4 + pp);
        #pragma unroll
        for (int q = 0; q < 16; q++)
            xr[pp][q] = g_x[row*512 + q*32 + lane];
    }
    __syncthreads();

    for (int o = 0; o < 45; o++) {
        const float* wr = &s_hw[o*512];
        float wv[16];
        #pragma unroll
        for (int q = 0; q < 16; q++) wv[q] = wr[q*32 + lane];
        #pragma unroll
        for (int pp = 0; pp < 4; pp++) {
            float s = 0.f;
            #pragma unroll
            for (int q = 0; q < 16; q++) s = fmaf(xr[pp][q], wv[q], s);
            #pragma unroll
            for (int off = 16; off > 0; off >>= 1) s += __shfl_xor_sync(FULLM, s, off);
            if (lane == 0) ovs[w*4 + pp][o] = s;
        }
    }
    __syncthreads();

    // decode: 32 positions x 9 anchors = 288 items
    for (int idx = t; idx < 288; idx += 256) {
        const int pl = idx / 9, a = idx % 9;
        const int pos = grp*32 + pl;
        const int i = pos >> 4, j = pos & 15;
        const float xc = (j + 0.5f) * 16.f, yc = (i + 0.5f) * 16.f;
        const float aw = c_AW[a], ah = c_AH[a];
        const float logit = ovs[pl][a] + cls_b[a];
        const float r0 = ovs[pl][9 + a*4 + 0] + reg_b[a*4 + 0];
        const float r1 = ovs[pl][9 + a*4 + 1] + reg_b[a*4 + 1];
        const float r2 = ovs[pl][9 + a*4 + 2] + reg_b[a*4 + 2];
        const float r3 = ovs[pl][9 + a*4 + 3] + reg_b[a*4 + 3];
        const float cx = r0*aw + xc, cy = r1*ah + yc;
        const float pw = expf(r2)*aw, ph = expf(r3)*ah;
        float x1 = fminf(fmaxf(cx - 0.5f*pw, 0.f), 256.f);
        float y1 = fminf(fmaxf(cy - 0.5f*ph, 0.f), 256.f);
        float x2 = fminf(fmaxf(cx + 0.5f*pw, 0.f), 256.f);
        float y2 = fminf(fmaxf(cy + 0.5f*ph, 0.f), 256.f);
        if (x2 - x1 < 1.f) x2 = x1 + 1.f;
        if (y2 - y1 < 1.f) y2 = y1 + 1.f;
        const int ai = pos*9 + a;
        g_scores[b*NANCH + ai] = 1.f / (1.f + expf(-logit));
        float* bp = &g_boxes[((size_t)b*NANCH + ai)*4];
        bp[0] = x1; bp[1] = y1; bp[2] = x2; bp[3] = y2;
    }
}

// ---------------- 3. per-batch top-30 (stable) + sequential NMS -----------------
__global__ __launch_bounds__(256) void topk_nms_kernel() {
    const int b = blockIdx.x, t = threadIdx.x;
    __shared__ float sc[NANCH];
    __shared__ float rv[256];
    __shared__ int   ri[256];
    __shared__ int   sel[KTOP];
    __shared__ float bx[KTOP][4];
    __shared__ int   keep[KTOP];
    for (int k = t; k < NANCH; k += 256) sc[k] = g_scores[b*NANCH + k];
    __syncthreads();
    for (int it = 0; it < KTOP; it++) {
        float bv = -3.f; int bi = NANCH;
        for (int k = t; k < NANCH; k += 256) {
            const float v = sc[k];
            if (v > bv || (v == bv && k < bi)) { bv = v; bi = k; }
        }
        rv[t] = bv; ri[t] = bi;
        __syncthreads();
        for (int s = 128; s > 0; s >>= 1) {
            if (t < s) {
                const float v2 = rv[t + s]; const int i2 = ri[t + s];
                if (v2 > rv[t] || (v2 == rv[t] && i2 < ri[t])) { rv[t] = v2; ri[t] = i2; }
            }
            __syncthreads();
        }
        if (t == 0) { sel[it] = ri[0]; sc[ri[0]] = -2.f; }
        __syncthreads();
    }
    if (t < KTOP) {
        const float* bp = &g_boxes[((size_t)b*NANCH + sel[t])*4];
        bx[t][0] = bp[0]; bx[t][1] = bp[1]; bx[t][2] = bp[2]; bx[t][3] = bp[3];
        keep[t] = 1;
    }
    __syncthreads();
    for (int ii = 0; ii < KTOP; ii++) {
        if (t < KTOP && t > ii && keep[ii]) {
            const float ax1 = bx[ii][0], ay1 = bx[ii][1], ax2 = bx[ii][2], ay2 = bx[ii][3];
            const float bx1 = bx[t][0], by1 = bx[t][1], bx2 = bx[t][2], by2 = bx[t][3];
            const float areaA = (ax2 - ax1) * (ay2 - ay1);
            const float areaB = (bx2 - bx1) * (by2 - by1);
            const float iw = fmaxf(fminf(ax2, bx2) - fmaxf(ax1, bx1), 0.f);
            const float ih = fmaxf(fminf(ay2, by2) - fmaxf(ay1, by1), 0.f);
            const float inter = iw * ih;
            const float iou = inter / (areaA + areaB - inter);
            if (iou > 0.85f) keep[t] = 0;
        }
        __syncthreads();
    }
    if (t < KTOP) {
        const int r = b*KTOP + t;
        g_rois[r*4 + 0] = bx[t][0];
        g_rois[r*4 + 1] = bx[t][1];
        g_rois[r*4 + 2] = bx[t][2];
        g_rois[r*4 + 3] = bx[t][3];
        g_valid[r] = keep[t];
    }
}

// ---------------- 4. integral image: warp-scan rows, tiled column scan ----------
__global__ __launch_bounds__(256) void integral_rows(const float* __restrict__ gt) {
    const int b = blockIdx.y, t = threadIdx.x;
    const int w = t >> 5, lane = t & 31;
    const int row = blockIdx.x * 8 + w;
    if (blockIdx.x == 0) {
        for (int idx = t; idx < 257; idx += 256)
            g_integral[((size_t)b*257)*257 + idx] = 0.f;
    }
    const float* gr = gt + (size_t)b*65536 + (size_t)row*256;
    float* Ir = g_integral + ((size_t)b*257 + row + 1)*257;
    if (lane == 0) Ir[0] = 0.f;
    float carry = 0.f;
    #pragma unroll
    for (int chunk = 0; chunk < 8; chunk++) {
        float v = gr[chunk*32 + lane];
        #pragma unroll
        for (int off = 1; off < 32; off <<= 1) {
            const float n = __shfl_up_sync(FULLM, v, off);
            if (lane >= off) v += n;
        }
        Ir[1 + chunk*32 + lane] = carry + v;
        carry += __shfl_sync(FULLM, v, 31);
    }
}

__global__ __launch_bounds__(256) void integral_cols() {
    __shared__ float tile[32][264];
    const int b = blockIdx.x, t = threadIdx.x;
    float* base = &g_integral[(size_t)b*257*257];
    float s0 = 0.f, s1 = 0.f;
    for (int ti = 0; ti < 8; ti++) {
        const int r0 = ti*32 + 1;
        #pragma unroll 4
        for (int rr = 0; rr < 32; rr++) {
            tile[rr][t] = base[(size_t)(r0 + rr)*257 + t];
            if (t == 0) tile[rr][256] = base[(size_t)(r0 + rr)*257 + 256];
        }
        __syncthreads();
        #pragma unroll 4
        for (int rr = 0; rr < 32; rr++) {
            s0 += tile[rr][t];  tile[rr][t] = s0;
            if (t == 0) { s1 += tile[rr][256]; tile[rr][256] = s1; }
        }
        __syncthreads();
        #pragma unroll 4
        for (int rr = 0; rr < 32; rr++) {
            base[(size_t)(r0 + rr)*257 + t] = tile[rr][t];
            if (t == 0) base[(size_t)(r0 + rr)*257 + 256] = tile[rr][256];
        }
        __syncthreads();
    }
}

// ---------------- 5. ROI-align mean (1024 ch, float4) + label -------------------
// Pooling skipped for NMS-suppressed ROIs (their proj rows are never read).
__global__ __launch_bounds__(256) void roialign_kernel(const float* __restrict__ clip) {
    const int r = blockIdx.x, t = threadIdx.x;
    const int b = r / KTOP;
    __shared__ int   o00[49], o01[49], o10[49], o11[49];
    __shared__ float w00[49], w01[49], w10[49], w11[49];
    __shared__ float roi[4];
    if (t < 4) roi[t] = g_rois[r*4 + t];
    __syncthreads();
    if (t == 0) {
        const int x1 = min(max((int)roi[0], 0), 256);
        const int y1 = min(max((int)roi[1], 0), 256);
        const int x2 = min(max((int)roi[2], 0), 256);
        const int y2 = min(max((int)roi[3], 0), 256);
        const float* I = &g_integral[(size_t)b*257*257];
        const float sI = I[y2*257 + x2] - I[y1*257 + x2] - I[y2*257 + x1] + I[y1*257 + x1];
        const int cnt = (y2 - y1) * (x2 - x1);
        g_labels[r] = (cnt > 0) && (sI / (float)max(cnt, 1) > 0.5f) ? 1 : 0;
    }
    if (!g_valid[r]) return;   // suppressed ROI: pooled/proj never consumed
    if (t < 49) {
        const int py = t / 7, px = t % 7;
        const float sc = 1.f / 16.f;
        const float x1f = roi[0]*sc, y1f = roi[1]*sc;
        const float rw = fmaxf(roi[2]*sc - x1f, 1.f);
        const float rh = fmaxf(roi[3]*sc - y1f, 1.f);
        const float X = x1f + (px + 0.5f) * (rw / 7.f);
        const float Y = y1f + (py + 0.5f) * (rh / 7.f);
        const bool ok = (Y > -1.f) && (Y < 16.f) && (X > -1.f) && (X < 16.f);
        const float Xc = fminf(fmaxf(X, 0.f), 15.f);
        const float Yc = fminf(fmaxf(Y, 0.f), 15.f);
        const int x0 = (int)floorf(Xc), y0 = (int)floorf(Yc);
        const int x1i = min(x0 + 1, 15), y1i = min(y0 + 1, 15);
        const float lx = Xc - (float)x0, ly = Yc - (float)y0;
        const float hx = 1.f - lx, hy = 1.f - ly;
        const float okf = ok ? 1.f : 0.f;
        o00[t] = (1 + y0*16  + x0 )*8192 + b*256;
        o01[t] = (1 + y0*16  + x1i)*8192 + b*256;
        o10[t] = (1 + y1i*16 + x0 )*8192 + b*256;
        o11[t] = (1 + y1i*16 + x1i)*8192 + b*256;
        w00[t] = hy*hx*okf; w01[t] = hy*lx*okf; w10[t] = ly*hx*okf; w11[t] = ly*lx*okf;
    }
    __syncthreads();
    const float4* clip4 = (const float4*)clip;
    float4 s = make_float4(0.f, 0.f, 0.f, 0.f);
    for (int p = 0; p < 49; p++) {
        const float4 a = clip4[o00[p] + t];
        const float4 bb = clip4[o01[p] + t];
        const float4 c = clip4[o10[p] + t];
        const float4 d = clip4[o11[p] + t];
        const float wa = w00[p], wb = w01[p], wc = w10[p], wd = w11[p];
        s.x += wa*a.x + wb*bb.x + wc*c.x + wd*d.x;
        s.y += wa*a.y + wb*bb.y + wc*c.y + wd*d.y;
        s.z += wa*a.z + wb*bb.z + wc*c.z + wd*d.z;
        s.w += wa*a.w + wb*bb.w + wc*c.w + wd*d.w;
    }
    const float inv = 1.f/49.f;
    float4* po = (float4*)&g_pooled[(size_t)r*1024];
    po[t] = make_float4(s.x*inv, s.y*inv, s.z*inv, s.w*inv);
}

// ---------------- 6. projection MLP, 4 ROIs per block, warp-per-output ----------
#define RPB 4
__global__ __launch_bounds__(256) void mlp_kernel(const float* __restrict__ w1,
                                                  const float* __restrict__ b1,
                                                  const float* __restrict__ w2,
                                                  const float* __restrict__ b2) {
    const int r0 = blockIdx.x * RPB, t = threadIdx.x;
    const int w = t >> 5, lane = t & 31;
    if (!(g_valid[r0] | g_valid[r0+1] | g_valid[r0+2] | g_valid[r0+3])) return;
    __shared__ float pr[RPB][1024];
    __shared__ float hs[RPB][256];
    __shared__ float ps[RPB][256];
    __shared__ float dn[RPB];
    for (int idx = t; idx < RPB*1024; idx += 256)
        pr[idx >> 10][idx & 1023] = g_pooled[(size_t)r0*1024 + idx];
    __syncthreads();
    for (int m = 0; m < 32; m++) {
        const int o = m*8 + w;
        float a0 = 0.f, a1 = 0.f, a2 = 0.f, a3 = 0.f;
        const float* wr = w1 + (size_t)o*1024;
        #pragma unroll 8
        for (int q = 0; q < 32; q++) {
            const float wv = wr[q*32 + lane];
            a0 = fmaf(wv, pr[0][q*32 + lane], a0);
            a1 = fmaf(wv, pr[1][q*32 + lane], a1);
            a2 = fmaf(wv, pr[2][q*32 + lane], a2);
            a3 = fmaf(wv, pr[3][q*32 + lane], a3);
        }
        #pragma unroll
        for (int off = 16; off > 0; off >>= 1) {
            a0 += __shfl_xor_sync(FULLM, a0, off);
            a1 += __shfl_xor_sync(FULLM, a1, off);
            a2 += __shfl_xor_sync(FULLM, a2, off);
            a3 += __shfl_xor_sync(FULLM, a3, off);
        }
        if (lane == 0) {
            const float bb = b1[o];
            hs[0][o] = fmaxf(a0 + bb, 0.f);
            hs[1][o] = fmaxf(a1 + bb, 0.f);
            hs[2][o] = fmaxf(a2 + bb, 0.f);
            hs[3][o] = fmaxf(a3 + bb, 0.f);
        }
    }
    __syncthreads();
    for (int m = 0; m < 32; m++) {
        const int o = m*8 + w;
        float a0 = 0.f, a1 = 0.f, a2 = 0.f, a3 = 0.f;
        const float* wr = w2 + (size_t)o*256;
        #pragma unroll
        for (int q = 0; q < 8; q++) {
            const float wv = wr[q*32 + lane];
            a0 = fmaf(wv, hs[0][q*32 + lane], a0);
            a1 = fmaf(wv, hs[1][q*32 + lane], a1);
            a2 = fmaf(wv, hs[2][q*32 + lane], a2);
            a3 = fmaf(wv, hs[3][q*32 + lane], a3);
        }
        #pragma unroll
        for (int off = 16; off > 0; off >>= 1) {
            a0 += __shfl_xor_sync(FULLM, a0, off);
            a1 += __shfl_xor_sync(FULLM, a1, off);
            a2 += __shfl_xor_sync(FULLM, a2, off);
            a3 += __shfl_xor_sync(FULLM, a3, off);
        }
        if (lane == 0) {
            const float bb = b2[o];
            ps[0][o] = a0 + bb; ps[1][o] = a1 + bb;
            ps[2][o] = a2 + bb; ps[3][o] = a3 + bb;
        }
    }
    __syncthreads();
    if (w < RPB) {
        float ss = 0.f;
        #pragma unroll
        for (int q = 0; q < 8; q++) {
            const float v = ps[w][q*32 + lane];
            ss = fmaf(v, v, ss);
        }
        #pragma unroll
        for (int off = 16; off > 0; off >>= 1) ss += __shfl_xor_sync(FULLM, ss, off);
        if (lane == 0) dn[w] = fmaxf(sqrtf(ss), 1e-12f);
    }
    __syncthreads();
    for (int idx = t; idx < RPB*256; idx += 256) {
        const int r = idx >> 8, o = idx & 255;
        g_proj[(size_t)(r0 + r)*256 + o] = ps[r][o] / dn[r];
    }
}

// ---------------- 7. SupCon loss, 4 anchors per block, warp-per-j ---------------
#define IPB 4
__global__ __launch_bounds__(256) void supcon_kernel() {
    const int i0 = blockIdx.x * IPB, t = threadIdx.x;
    const int w = t >> 5, lane = t & 31;
    __shared__ float nfi[IPB][256];
    __shared__ int   jv[NROI];
    __shared__ int   jl[NROI];
    __shared__ float w_ps[8][IPB], w_ds[8][IPB];
    __shared__ int   w_pc[8][IPB];
    for (int idx = t; idx < IPB*256; idx += 256)
        nfi[idx >> 8][idx & 255] = g_proj[(size_t)i0*256 + idx];
    for (int idx = t; idx < NROI; idx += 256) { jv[idx] = g_valid[idx]; jl[idx] = g_labels[idx]; }
    __syncthreads();

    int li[IPB];
    #pragma unroll
    for (int i = 0; i < IPB; i++) li[i] = jl[i0 + i];

    float ps[IPB] = {0.f, 0.f, 0.f, 0.f};
    float ds[IPB] = {0.f, 0.f, 0.f, 0.f};
    int   pc[IPB] = {0, 0, 0, 0};

    for (int j = w; j < NROI; j += 8) {
        if (!jv[j]) continue;
        const float* pj = &g_proj[(size_t)j*256];
        float d0 = 0.f, d1 = 0.f, d2 = 0.f, d3 = 0.f;
        #pragma unroll
        for (int q = 0; q < 8; q++) {
            const float v = pj[q*32 + lane];
            d0 = fmaf(v, nfi[0][q*32 + lane], d0);
            d1 = fmaf(v, nfi[1][q*32 + lane], d1);
            d2 = fmaf(v, nfi[2][q*32 + lane], d2);
            d3 = fmaf(v, nfi[3][q*32 + lane], d3);
        }
        #pragma unroll
        for (int off = 16; off > 0; off >>= 1) {
            d0 += __shfl_xor_sync(FULLM, d0, off);
            d1 += __shfl_xor_sync(FULLM, d1, off);
            d2 += __shfl_xor_sync(FULLM, d2, off);
            d3 += __shfl_xor_sync(FULLM, d3, off);
        }
        const int lj = jl[j];
        float dd[IPB] = {d0, d1, d2, d3};
        #pragma unroll
        for (int i = 0; i < IPB; i++) {
            if (j == i0 + i) continue;
            const float es = expf(dd[i] / 0.07f);
            ds[i] += es;
            if (lj == li[i]) { ps[i] += es; pc[i]++; }
        }
    }
    if (lane == 0) {
        #pragma unroll
        for (int i = 0; i < IPB; i++) { w_ps[w][i] = ps[i]; w_ds[w][i] = ds[i]; w_pc[w][i] = pc[i]; }
    }
    __syncthreads();
    if (t < IPB) {
        float P = 0.f, D = 0.f; int C = 0;
        #pragma unroll
        for (int ww = 0; ww < 8; ww++) { P += w_ps[ww][t]; D += w_ds[ww][t]; C += w_pc[ww][t]; }
        const float ratio = P / (D + 1e-12f);
        const float l = -logf(ratio + 1e-12f);
        const int act = jv[i0 + t] && (C > 0);
        g_li[i0 + t] = act ? l : 0.f;
        g_active[i0 + t] = act;
    }
}

// ---------------- 8. final reduction --------------------------------------------
__global__ __launch_bounds__(256) void final_kernel(float* __restrict__ out) {
    const int t = threadIdx.x;
    __shared__ float rs[256];
    __shared__ int   rc[256];
    float s = 0.f; int c = 0;
    for (int k = t; k < NROI; k += 256) { s += g_li[k]; c += g_active[k]; }
    rs[t] = s; rc[t] = c;
    __syncthreads();
    for (int st = 128; st > 0; st >>= 1) {
        if (t < st) { rs[t] += rs[t + st]; rc[t] += rc[t + st]; }
        __syncthreads();
    }
    if (t == 0) out[0] = (rc[0] > 0) ? rs[0] / (float)max(rc[0], 1) : 0.f;
}

// ---------------- launch --------------------------------------------------------
extern "C" void kernel_launch(void* const* d_in, const int* in_sizes, int n_in,
                              void* d_out, int out_size) {
    const float* clip   = (const float*)d_in[0];
    const float* gt     = (const float*)d_in[1];
    const float* conv_w = (const float*)d_in[2];
    const float* conv_b = (const float*)d_in[3];
    const float* cls_w  = (const float*)d_in[4];
    const float* cls_b  = (const float*)d_in[5];
    const float* reg_w  = (const float*)d_in[6];
    const float* reg_b  = (const float*)d_in[7];
    const float* w1     = (const float*)d_in[8];
    const float* b1     = (const float*)d_in[9];
    const float* w2     = (const float*)d_in[10];
    const float* b2     = (const float*)d_in[11];
    float* out = (float*)d_out;

    const int head_smem = 45*512*sizeof(float);   // 92160 B
    cudaFuncSetAttribute(head_kernel, cudaFuncAttributeMaxDynamicSharedMemorySize, head_smem);

    conv_kernel<<<dim3(16, 32), 128>>>(clip, conv_w, conv_b);
    integral_rows<<<dim3(32, 32), 256>>>(gt);
    integral_cols<<<32, 256>>>();
    head_kernel<<<dim3(8, 32), 256, head_smem>>>(cls_w, cls_b, reg_w, reg_b);
    topk_nms_kernel<<<32, 256>>>();
    roialign_kernel<<<NROI, 256>>>(clip);
    mlp_kernel<<<NROI/RPB, 256>>>(w1, b1, w2, b2);
    supcon_kernel<<<NROI/IPB, 256>>>();
    final_kernel<<<1, 256>>>(out);
}